// round 12
// baseline (speedup 1.0000x reference)
#include <cuda_runtime.h>
#include <cuda_fp16.h>
#include <mma.h>
#include <cstdint>

using namespace nvcuda;

// Problem constants
#define B_DIM      32
#define S_DIM      2048
#define H_DIM      4096
#define R_DIM      64
#define N_ADAPT    16
#define TILE_M     128
#define KC         64                  // K elements per chunk (locked)
#define KSPLIT     2
#define NCHUNK_PER (H_DIM / KC / KSPLIT)   // 32 chunks per CTA
#define NTHREADS   256
#define OUT_ELEMS  (B_DIM * S_DIM * R_DIM) // 4,194,304

// SMEM (half): row stride 72 halves = 144 B (conflict-free, ldm mult of 8)
#define LDH        72
#define X_STAGE_H  (TILE_M * LDH)                 // 9216 halves = 18432 B
#define W_STAGE_H  (R_DIM * LDH)                  // 4608 halves = 9216 B
#define STAGE_H    (X_STAGE_H + W_STAGE_H)        // 13824 halves
#define STAGE_B    (STAGE_H * 2)                  // 27648 B
#define SMEM_TOTAL (2 * STAGE_B)                  // 55296 B (x2 CTAs = 110592)

// Static scratch: pre-converted fp16 weights (8 MB) + split-K partials (16.8 MB)
__device__ __half g_wh[N_ADAPT * R_DIM * H_DIM];
__device__ float  g_partial[OUT_ELEMS];

__device__ __forceinline__ uint32_t smem_u32(const void* p) {
    uint32_t r;
    asm("{ .reg .u64 t; cvta.to.shared.u64 t, %1; cvt.u32.u64 %0, t; }"
        : "=r"(r) : "l"(p));
    return r;
}

__device__ __forceinline__ void sts64(uint32_t addr, uint32_t a, uint32_t b) {
    asm volatile("st.shared.v2.b32 [%0], {%1, %2};"
                 :: "r"(addr), "r"(a), "r"(b));
}

__device__ __forceinline__ void cp_async16(uint32_t dst, const void* src) {
    asm volatile("cp.async.cg.shared.global [%0], [%1], 16;"
                 :: "r"(dst), "l"(src) : "memory");
}
#define CP_COMMIT() asm volatile("cp.async.commit_group;" ::: "memory")
#define CP_WAIT0()  asm volatile("cp.async.wait_group 0;" ::: "memory")

// ---- kernel 1: convert all adapter weights f32 -> f16 (RN) ----------------
__global__ void convert_w_kernel(const float4* __restrict__ w) {
    int i = blockIdx.x * blockDim.x + threadIdx.x;   // one float4 each
    float4 v = w[i];
    __half2 h0 = __floats2half2_rn(v.x, v.y);
    __half2 h1 = __floats2half2_rn(v.z, v.w);
    uint2 p;
    p.x = *(const uint32_t*)&h0;
    p.y = *(const uint32_t*)&h1;
    ((uint2*)g_wh)[i] = p;
}

// ---- kernel 3: out += partial (split-K reduce, no atomics) -----------------
__global__ void reduce_kernel(float4* __restrict__ out) {
    int i = blockIdx.x * blockDim.x + threadIdx.x;   // one float4 each
    float4 o = out[i];
    float4 p = ((const float4*)g_partial)[i];
    o.x += p.x; o.y += p.y; o.z += p.z; o.w += p.w;
    out[i] = o;
}

// ---- kernel 2: gathered GEMM, fp16 HMMA, KC=64, split-K=2 ------------------
__global__ void __launch_bounds__(NTHREADS, 2)
multilora_fp16_sk2_kernel(const float* __restrict__ x,
                          const int* __restrict__ adapter_ids,
                          float* __restrict__ out) {
    extern __shared__ __align__(16) __half smem[];
    const uint32_t smem_base = smem_u32(smem);

    const int tid = threadIdx.x;
    const int wid = tid >> 5;

    const int mtile = blockIdx.x;       // 0..15
    const int b     = blockIdx.y;       // 0..31
    const int kz    = blockIdx.z;       // 0..1
    const int m0    = mtile * TILE_M;
    const int aid   = __ldg(adapter_ids + b);
    const size_t k0 = (size_t)kz * NCHUNK_PER * KC;   // 0 or 2048

    // ---- x producer mapping: 2048 float4 quads / chunk over 256 thr = 8 each
    const float* xg[8];
    uint32_t xoff[8];
    #pragma unroll
    for (int j = 0; j < 8; j++) {
        int i = tid + j * NTHREADS;
        int row = i >> 4, q = i & 15;
        xg[j]   = x + ((size_t)(b * S_DIM + m0 + row)) * H_DIM + k0 + q * 4;
        xoff[j] = (uint32_t)((row * LDH + q * 4) * 2);
    }

    // ---- w cp.async mapping: 512 16B-copies / chunk over 256 thr = 2 each
    const __half* whbase = g_wh + (size_t)aid * R_DIM * H_DIM + k0;
    const __half* wg[2];
    uint32_t woff[2];
    #pragma unroll
    for (int j = 0; j < 2; j++) {
        int i = tid + j * NTHREADS;
        int row = i >> 3, seg = i & 7;
        wg[j]   = whbase + (size_t)row * H_DIM + seg * 8;
        woff[j] = (uint32_t)((X_STAGE_H + row * LDH + seg * 8) * 2);
    }

    // ---- consumer mapping: 8 warps, 32x32 warp tiles (4 along M, 2 along N)
    const int wm = wid >> 1;
    const int wn = wid & 1;

    wmma::fragment<wmma::accumulator, 16, 16, 16, float> acc[2][2];
    #pragma unroll
    for (int fi = 0; fi < 2; fi++)
        #pragma unroll
        for (int fj = 0; fj < 2; fj++)
            wmma::fill_fragment(acc[fi][fj], 0.0f);

    // ---- prologue: w(0) into stage 0 via cp.async; x(0) into registers
    #pragma unroll
    for (int j = 0; j < 2; j++)
        cp_async16(smem_base + woff[j], wg[j]);
    CP_COMMIT();

    float4 cur[8];
    #pragma unroll
    for (int j = 0; j < 8; j++)
        cur[j] = *(const float4*)(xg[j]);

    for (int kc = 0; kc < NCHUNK_PER; kc++) {
        const int s = kc & 1;
        const uint32_t sb = smem_base + s * STAGE_B;
        __half* xs = smem + s * STAGE_H;
        __half* ws = xs + X_STAGE_H;

        // x: RN convert + STS.64 (empties cur)
        #pragma unroll
        for (int j = 0; j < 8; j++) {
            __half2 h0 = __floats2half2_rn(cur[j].x, cur[j].y);
            __half2 h1 = __floats2half2_rn(cur[j].z, cur[j].w);
            sts64(sb + xoff[j],
                  *(const uint32_t*)&h0, *(const uint32_t*)&h1);
        }

        // x loads for chunk kc+1 (land during barrier + 4 k-steps below)
        if (kc + 1 < NCHUNK_PER) {
            #pragma unroll
            for (int j = 0; j < 8; j++)
                cur[j] = *(const float4*)(xg[j] + (size_t)(kc + 1) * KC);
        }

        // w(kc) must be resident (only group(kc) can still be pending)
        CP_WAIT0();

        // Barrier: RAW on stage s; proves WMMA(kc-1) done -> s^1 writable.
        __syncthreads();

        // w(kc+1) via cp.async into stage s^1
        if (kc + 1 < NCHUNK_PER) {
            const uint32_t sb1 = smem_base + (s ^ 1) * STAGE_B;
            #pragma unroll
            for (int j = 0; j < 2; j++)
                cp_async16(sb1 + woff[j], wg[j] + (size_t)(kc + 1) * KC);
        }
        CP_COMMIT();

        // compute: 4 k-steps of m16n16k16
        #pragma unroll
        for (int kk = 0; kk < KC; kk += 16) {
            wmma::fragment<wmma::matrix_a, 16, 16, 16, __half,
                           wmma::row_major> af[2];
            wmma::fragment<wmma::matrix_b, 16, 16, 16, __half,
                           wmma::col_major> bf[2];
            #pragma unroll
            for (int fi = 0; fi < 2; fi++)
                wmma::load_matrix_sync(af[fi],
                    xs + (wm * 32 + fi * 16) * LDH + kk, LDH);
            #pragma unroll
            for (int fj = 0; fj < 2; fj++)
                wmma::load_matrix_sync(bf[fj],
                    ws + (wn * 32 + fj * 16) * LDH + kk, LDH);
            #pragma unroll
            for (int fi = 0; fi < 2; fi++)
                #pragma unroll
                for (int fj = 0; fj < 2; fj++)
                    wmma::mma_sync(acc[fi][fj], af[fi], bf[fj], acc[fi][fj]);
        }
    }

    // ---- epilogue: kz=0 -> out, kz=1 -> partial scratch (no atomics)
    float* dst = (kz == 0) ? out : g_partial;
    float* obase = dst + ((size_t)(b * S_DIM + m0 + wm * 32)) * R_DIM + wn * 32;
    #pragma unroll
    for (int fi = 0; fi < 2; fi++)
        #pragma unroll
        for (int fj = 0; fj < 2; fj++)
            wmma::store_matrix_sync(obase + (size_t)fi * 16 * R_DIM + fj * 16,
                                    acc[fi][fj], R_DIM, wmma::mem_row_major);
}

extern "C" void kernel_launch(void* const* d_in, const int* in_sizes, int n_in,
                              void* d_out, int out_size) {
    const float* x   = (const float*)d_in[0];
    const int*   ids = (const int*)d_in[1];
    const float* w   = (const float*)d_in[2];
    float* out = (float*)d_out;

    const int b = in_sizes[1];   // number of requests (32)

    // 1) convert adapter weights f32 -> f16 once per launch (~3.5 us)
    const int n4 = (N_ADAPT * R_DIM * H_DIM) / 4;    // 1,048,576 float4s
    convert_w_kernel<<<n4 / 256, 256>>>((const float4*)w);

    // 2) main gathered GEMM, split-K=2
    cudaFuncSetAttribute(multilora_fp16_sk2_kernel,
                         cudaFuncAttributeMaxDynamicSharedMemorySize, SMEM_TOTAL);
    dim3 grid(S_DIM / TILE_M, b, KSPLIT);
    multilora_fp16_sk2_kernel<<<grid, NTHREADS, SMEM_TOTAL>>>(x, ids, out);

    // 3) out += partial (~8 us)
    const int o4 = (b * S_DIM * R_DIM) / 4;          // 1,048,576 float4s
    reduce_kernel<<<o4 / 256, 256>>>((float4*)out);
}